// round 13
// baseline (speedup 1.0000x reference)
#include <cuda_runtime.h>
#include <math.h>
#include <stdint.h>

#define TT   2048
#define DM   2048
#define NH   32
#define NKV  8
#define HD   64

// ---------------- scratch ----------------
// k of X / O / W permuted within 16-groups: phys = 4*(j&3)+2*((j>>3)&1)+((j>>2)&1)
__device__ float g_X[TT * DM];          // x, tf32, k-permuted
__device__ float g_WT[5120 * DM];       // [n][k] transposed+permuted tf32
__device__ float g_Q[TT * DM];          // RoPE'd, tf32, logical
__device__ float g_K[NKV * TT * HD];    // RoPE'd, tf32, logical
__device__ float g_V[NKV * TT * HD];    // tf32, logical
__device__ float g_O[TT * DM];          // attn out, tf32, k-permuted

__device__ __forceinline__ int perm16(int j) {
    return 4 * (j & 3) + 2 * ((j >> 3) & 1) + ((j >> 2) & 1);
}
__device__ __forceinline__ float f2tf32(float x) {
    float y; asm("cvt.rna.tf32.f32 %0, %1;" : "=f"(y) : "f"(x)); return y;
}
__device__ __forceinline__ void mma_tf32(float* d, const uint32_t* a, const uint32_t* b) {
    asm volatile(
        "mma.sync.aligned.m16n8k8.row.col.f32.tf32.tf32.f32 "
        "{%0,%1,%2,%3}, {%4,%5,%6,%7}, {%8,%9}, {%0,%1,%2,%3};"
        : "+f"(d[0]), "+f"(d[1]), "+f"(d[2]), "+f"(d[3])
        : "r"(a[0]), "r"(a[1]), "r"(a[2]), "r"(a[3]), "r"(b[0]), "r"(b[1]));
}
__device__ __forceinline__ uint32_t smem_u32(const void* p) {
    uint32_t a;
    asm("{ .reg .u64 t; cvta.to.shared.u64 t, %1; cvt.u32.u64 %0, t; }" : "=r"(a) : "l"(p));
    return a;
}
#define CPA16(dst, src) asm volatile("cp.async.cg.shared.global [%0], [%1], 16;" :: "r"(dst), "l"(src))
#define CP_COMMIT()     asm volatile("cp.async.commit_group;" ::: "memory")
#define CP_WAIT(n)      asm volatile("cp.async.wait_group %0;" :: "n"(n) : "memory")

// ---------------------------------------------------------------------------
// Pre-pass A: x -> g_X, tf32 + k-perm within 16-groups.
// ---------------------------------------------------------------------------
__global__ __launch_bounds__(256)
void conv_x(const float* __restrict__ src)
{
    const size_t base = ((size_t)blockIdx.x * 256 + threadIdx.x) * 16;
    float4 v0 = *(const float4*)(src + base + 0);
    float4 v1 = *(const float4*)(src + base + 4);
    float4 v2 = *(const float4*)(src + base + 8);
    float4 v3 = *(const float4*)(src + base + 12);
    float4 o;
    o = make_float4(f2tf32(v0.x), f2tf32(v1.x), f2tf32(v2.x), f2tf32(v3.x));
    *(float4*)(g_X + base + 0) = o;
    o = make_float4(f2tf32(v0.y), f2tf32(v1.y), f2tf32(v2.y), f2tf32(v3.y));
    *(float4*)(g_X + base + 4) = o;
    o = make_float4(f2tf32(v0.z), f2tf32(v1.z), f2tf32(v2.z), f2tf32(v3.z));
    *(float4*)(g_X + base + 8) = o;
    o = make_float4(f2tf32(v0.w), f2tf32(v1.w), f2tf32(v2.w), f2tf32(v3.w));
    *(float4*)(g_X + base + 12) = o;
}

// ---------------------------------------------------------------------------
// Pre-pass B (fused): all 4 weights -> g_WT, transposed + tf32 + k-perm.
// ---------------------------------------------------------------------------
__global__ __launch_bounds__(256)
void conv_wall(const float* __restrict__ Wq, const float* __restrict__ Wk,
               const float* __restrict__ Wv, const float* __restrict__ Wo)
{
    __shared__ float tile[32][33];
    const int bx = blockIdx.x;
    const float* src; int N, rowbase, n0;
    if (bx < 64)      { src = Wq; N = 2048; rowbase = 0;    n0 = bx * 32; }
    else if (bx < 80) { src = Wk; N = 512;  rowbase = 2048; n0 = (bx - 64) * 32; }
    else if (bx < 96) { src = Wv; N = 512;  rowbase = 2560; n0 = (bx - 80) * 32; }
    else              { src = Wo; N = 2048; rowbase = 3072; n0 = (bx - 96) * 32; }

    const int tx = threadIdx.x & 31, ty = threadIdx.x >> 5;
    const int k0 = blockIdx.y * 32;
#pragma unroll
    for (int i = 0; i < 4; i++)
        tile[ty + 8 * i][tx] = src[(size_t)(k0 + ty + 8 * i) * N + n0 + tx];
    __syncthreads();
    const int pk = (tx & 16) | perm16(tx & 15);
#pragma unroll
    for (int i = 0; i < 4; i++) {
        const int nl = ty + 8 * i;
        g_WT[(size_t)(rowbase + n0 + nl) * DM + k0 + pk] = f2tf32(tile[tx][nl]);
    }
}

// ---------------------------------------------------------------------------
// TF32 GEMM, 128x128x32 CTA tile, FOUR warps with 64x64 warp tiles,
// 2-stage cp.async, LDS.128 fragment loads (XOR-swizzled smem).
// ---------------------------------------------------------------------------
template <bool QKV>
__global__ __launch_bounds__(128, 2)
void gemm_tc(float* __restrict__ Cout, const float* __restrict__ freqs)
{
    __shared__ __align__(16) float As[2][128][32];
    __shared__ __align__(16) float Bs[2][128][32];

    const int tid  = threadIdx.x;
    const int lane = tid & 31;
    const int warp = tid >> 5;              // 0..3
    const int wm0  = (warp & 1) * 64;
    const int wn0  = (warp >> 1) * 64;      // 0 or 64
    const int grp  = lane >> 2;
    const int tig  = lane & 3;
    const int row0 = blockIdx.y * 128;
    const int col0g = blockIdx.x * 128;

    const float* A = QKV ? g_X : g_O;
    const float* Bw = g_WT + (size_t)((QKV ? 0 : 3072) + col0g) * DM;

    const uint32_t aBase = smem_u32(&As[0][0][0]);
    const uint32_t bBase = smem_u32(&Bs[0][0][0]);

    // staging: 128 threads, 8 A-chunks + 8 B-chunks each (rows it*16 + tid>>3)
    const int st = tid & 7;
    const float* Aptr = A + (size_t)row0 * DM + st * 4;
    const float* Bptr = Bw + st * 4;

#define STAGE(buf, k0)                                                        \
    {                                                                         \
        _Pragma("unroll")                                                     \
        for (int it = 0; it < 8; it++) {                                      \
            const int rw = it * 16 + (tid >> 3);                              \
            const uint32_t doff = (uint32_t)(buf) * 16384u + rw * 128u +      \
                                  ((uint32_t)(st ^ ((rw & 1) << 2))) * 16u;   \
            CPA16(aBase + doff, Aptr + (size_t)rw * DM + (k0));               \
            CPA16(bBase + doff, Bptr + (size_t)rw * DM + (k0));               \
        }                                                                     \
    }

    STAGE(0, 0);
    CP_COMMIT();

    float acc[4][8][4];
#pragma unroll
    for (int mt = 0; mt < 4; mt++)
#pragma unroll
        for (int nt = 0; nt < 8; nt++)
#pragma unroll
            for (int u = 0; u < 4; u++) acc[mt][nt][u] = 0.f;

    const int par = (grp & 1) << 2;

    for (int s = 0; s < 64; s++) {
        const int cur = s & 1;
        if (s + 1 < 64) {
            STAGE((s + 1) & 1, (s + 1) * 32);
            CP_COMMIT();
            CP_WAIT(1);
        } else {
            CP_WAIT(0);
        }
        __syncthreads();

#pragma unroll
        for (int c = 0; c < 2; c++) {
            const int q = (((c << 2) + tig) ^ par) << 2;
            float4 Bf[8];
#pragma unroll
            for (int nt = 0; nt < 8; nt++)
                Bf[nt] = *(const float4*)&Bs[cur][wn0 + nt * 8 + grp][q];
#pragma unroll
            for (int mt = 0; mt < 4; mt++) {
                const int r = wm0 + mt * 16 + grp;
                float4 A0 = *(const float4*)&As[cur][r][q];
                float4 A1 = *(const float4*)&As[cur][r + 8][q];
                uint32_t ae[4] = {__float_as_uint(A0.x), __float_as_uint(A1.x),
                                  __float_as_uint(A0.y), __float_as_uint(A1.y)};
                uint32_t ao[4] = {__float_as_uint(A0.z), __float_as_uint(A1.z),
                                  __float_as_uint(A0.w), __float_as_uint(A1.w)};
#pragma unroll
                for (int nt = 0; nt < 8; nt++) {
                    uint32_t be[2] = {__float_as_uint(Bf[nt].x), __float_as_uint(Bf[nt].y)};
                    mma_tf32(acc[mt][nt], ae, be);
                }
#pragma unroll
                for (int nt = 0; nt < 8; nt++) {
                    uint32_t bo[2] = {__float_as_uint(Bf[nt].z), __float_as_uint(Bf[nt].w)};
                    mma_tf32(acc[mt][nt], ao, bo);
                }
            }
        }
        __syncthreads();
    }
#undef STAGE

#pragma unroll
    for (int mt = 0; mt < 4; mt++) {
#pragma unroll
        for (int nt = 0; nt < 8; nt++) {
            const int rb = row0 + wm0 + mt * 16 + grp;
            const int cb = col0g + wn0 + nt * 8 + tig * 2;
#pragma unroll
            for (int half = 0; half < 2; half++) {
                const int r = rb + half * 8;
                const float v0 = acc[mt][nt][half * 2 + 0];
                const float v1 = acc[mt][nt][half * 2 + 1];
                if (!QKV) {
                    *(float2*)(Cout + (size_t)r * DM + cb) = make_float2(v0, v1);
                } else if (cb >= 2560) {   // V
                    const int lc = cb - 2560;
                    const int kv = lc >> 6, d = lc & 63;
                    *(float2*)(g_V + ((size_t)kv * TT + r) * HD + d) =
                        make_float2(f2tf32(v0), f2tf32(v1));
                } else {                   // Q or K: RoPE (logical layout)
                    const int lc = (cb >= 2048) ? cb - 2048 : cb;
                    const int d = lc & 63;
                    const float cs = freqs[(size_t)r * HD + d];
                    const float sn = freqs[(size_t)TT * HD + (size_t)r * HD + d];
                    const float o0 = f2tf32(v0 * cs - v1 * sn);
                    const float o1 = f2tf32(v1 * cs + v0 * sn);
                    if (cb < 2048) {
                        *(float2*)(g_Q + (size_t)r * DM + cb) = make_float2(o0, o1);
                    } else {
                        const int kv = lc >> 6;
                        *(float2*)(g_K + ((size_t)kv * TT + r) * HD + d) = make_float2(o0, o1);
                    }
                }
            }
        }
    }
}

// ---------------------------------------------------------------------------
// Tensor-core flash attention (R11-exact), mt=2: CTA = 128 queries x 1 head.
// ---------------------------------------------------------------------------
__global__ __launch_bounds__(128, 2)
void attn_tc_kernel()
{
    __shared__ __align__(16) float Ks[2][64][68];
    __shared__ __align__(16) float Vs[2][64][68];

    const int h   = blockIdx.x;
    const int qb  = (TT / 128 - 1) - blockIdx.y;   // heavy first
    const int kvh = h >> 2;
    const int tid  = threadIdx.x;
    const int lane = tid & 31;
    const int warp = tid >> 5;
    const int wm0  = warp * 32;
    const int grp  = lane >> 2;
    const int tig  = lane & 3;

    const float* kbase = g_K + (size_t)kvh * TT * HD;
    const float* vbase = g_V + (size_t)kvh * TT * HD;

    {
        const float* qsrc = g_Q + ((size_t)(qb * 128)) * DM + h * HD;
#pragma unroll
        for (int i = 0; i < 8; i++) {
            const int j = i * 128 + tid;
            const int row = j >> 4, c4 = (j & 15) * 4;
            float4 v = *(const float4*)(qsrc + (size_t)row * DM + c4);
            Ks[0][row][c4 + 0] = v.x * 0.125f;
            Ks[0][row][c4 + 1] = v.y * 0.125f;
            Ks[0][row][c4 + 2] = v.z * 0.125f;
            Ks[0][row][c4 + 3] = v.w * 0.125f;
            float4 w = *(const float4*)(qsrc + (size_t)(row + 64) * DM + c4);
            Vs[0][row][c4 + 0] = w.x * 0.125f;
            Vs[0][row][c4 + 1] = w.y * 0.125f;
            Vs[0][row][c4 + 2] = w.z * 0.125f;
            Vs[0][row][c4 + 3] = w.w * 0.125f;
        }
    }
    __syncthreads();

    uint32_t qf[2][8][4];
#pragma unroll
    for (int mt = 0; mt < 2; mt++) {
        const int rg = wm0 + 16 * mt;
        const float (*Qt)[68] = (rg < 64) ? Ks[0] : Vs[0];
        const int rb = rg & 63;
#pragma unroll
        for (int ks = 0; ks < 8; ks++) {
            qf[mt][ks][0] = __float_as_uint(Qt[rb + grp][8 * ks + tig]);
            qf[mt][ks][1] = __float_as_uint(Qt[rb + grp + 8][8 * ks + tig]);
            qf[mt][ks][2] = __float_as_uint(Qt[rb + grp][8 * ks + tig + 4]);
            qf[mt][ks][3] = __float_as_uint(Qt[rb + grp + 8][8 * ks + tig + 4]);
        }
    }
    __syncthreads();

    const int krow = tid >> 4;
    const int kc4  = (tid & 15) * 4;
    const uint32_t kDst = smem_u32(&Ks[0][krow][kc4]);
    const uint32_t vDst = smem_u32(&Vs[0][krow][kc4]);
    const uint32_t bufStride = 64 * 68 * 4;
    const float* kSrc = kbase + (size_t)krow * HD + kc4;
    const float* vSrc = vbase + (size_t)krow * HD + kc4;

#pragma unroll
    for (int i = 0; i < 8; i++) CPA16(kDst + i * 8 * 272, kSrc + (size_t)(8 * i) * HD);
#pragma unroll
    for (int i = 0; i < 8; i++) CPA16(vDst + i * 8 * 272, vSrc + (size_t)(8 * i) * HD);
    CP_COMMIT();

    float acc[2][8][4];
#pragma unroll
    for (int mt = 0; mt < 2; mt++)
#pragma unroll
        for (int nt = 0; nt < 8; nt++)
#pragma unroll
            for (int u = 0; u < 4; u++) acc[mt][nt][u] = 0.f;
    float m[2][2] = {{-1e30f, -1e30f}, {-1e30f, -1e30f}};
    float l[2][2] = {{0.f, 0.f}, {0.f, 0.f}};

    const int src0 = (lane & ~3) + (tig >> 1);
    const int src1 = src0 + 2;
    const bool odd = tig & 1;

    const int ntiles = 2 * qb + 2;

    for (int kt = 0; kt < ntiles; kt++) {
        const int cur = kt & 1;
        if (kt + 1 < ntiles) {
            const int nb = (kt + 1) & 1;
            const size_t off = (size_t)(kt + 1) * 64 * HD;
#pragma unroll
            for (int i = 0; i < 8; i++)
                CPA16(kDst + nb * bufStride + i * 8 * 272, kSrc + off + (size_t)(8 * i) * HD);
#pragma unroll
            for (int i = 0; i < 8; i++)
                CPA16(vDst + nb * bufStride + i * 8 * 272, vSrc + off + (size_t)(8 * i) * HD);
            CP_COMMIT();
            CP_WAIT(1);
        } else {
            CP_WAIT(0);
        }
        __syncthreads();

        float s[2][8][4];
#pragma unroll
        for (int mt = 0; mt < 2; mt++)
#pragma unroll
            for (int nt = 0; nt < 8; nt++)
#pragma unroll
                for (int u = 0; u < 4; u++) s[mt][nt][u] = 0.f;

#pragma unroll
        for (int ks = 0; ks < 8; ks++) {
#pragma unroll
            for (int nt = 0; nt < 8; nt++) {
                uint32_t b[2];
                b[0] = __float_as_uint(Ks[cur][8 * nt + grp][8 * ks + tig]);
                b[1] = __float_as_uint(Ks[cur][8 * nt + grp][8 * ks + tig + 4]);
                mma_tf32(s[0][nt], qf[0][ks], b);
                mma_tf32(s[1][nt], qf[1][ks], b);
            }
        }

        if (kt >= 2 * qb) {
#pragma unroll
            for (int mt = 0; mt < 2; mt++) {
                const int r0 = 128 * qb + wm0 + 16 * mt + grp;
                const int r1 = r0 + 8;
#pragma unroll
                for (int nt = 0; nt < 8; nt++) {
                    const int c = 64 * kt + 8 * nt + 2 * tig;
                    if (c > r0)     s[mt][nt][0] = -1e30f;
                    if (c + 1 > r0) s[mt][nt][1] = -1e30f;
                    if (c > r1)     s[mt][nt][2] = -1e30f;
                    if (c + 1 > r1) s[mt][nt][3] = -1e30f;
                }
            }
        }

#pragma unroll
        for (int mt = 0; mt < 2; mt++) {
            float t0 = -1e30f, t1 = -1e30f;
#pragma unroll
            for (int nt = 0; nt < 8; nt++) {
                t0 = fmaxf(t0, fmaxf(s[mt][nt][0], s[mt][nt][1]));
                t1 = fmaxf(t1, fmaxf(s[mt][nt][2], s[mt][nt][3]));
            }
            t0 = fmaxf(t0, __shfl_xor_sync(0xffffffffu, t0, 1));
            t0 = fmaxf(t0, __shfl_xor_sync(0xffffffffu, t0, 2));
            t1 = fmaxf(t1, __shfl_xor_sync(0xffffffffu, t1, 1));
            t1 = fmaxf(t1, __shfl_xor_sync(0xffffffffu, t1, 2));

            const float mn0 = fmaxf(m[mt][0], t0), mn1 = fmaxf(m[mt][1], t1);
            const float cr0 = __expf(m[mt][0] - mn0), cr1 = __expf(m[mt][1] - mn1);
            m[mt][0] = mn0; m[mt][1] = mn1;
            l[mt][0] *= cr0; l[mt][1] *= cr1;
#pragma unroll
            for (int nt = 0; nt < 8; nt++) {
                acc[mt][nt][0] *= cr0; acc[mt][nt][1] *= cr0;
                acc[mt][nt][2] *= cr1; acc[mt][nt][3] *= cr1;
            }
#pragma unroll
            for (int nt = 0; nt < 8; nt++) {
                float p0 = f2tf32(__expf(s[mt][nt][0] - mn0));
                float p1 = f2tf32(__expf(s[mt][nt][1] - mn0));
                float p2 = f2tf32(__expf(s[mt][nt][2] - mn1));
                float p3 = f2tf32(__expf(s[mt][nt][3] - mn1));
                l[mt][0] += p0 + p1; l[mt][1] += p2 + p3;
                s[mt][nt][0] = p0; s[mt][nt][1] = p1; s[mt][nt][2] = p2; s[mt][nt][3] = p3;
            }
        }

#pragma unroll
        for (int ks = 0; ks < 8; ks++) {
            uint32_t a0[4], a1[4];
#pragma unroll
            for (int mt = 0; mt < 2; mt++) {
                float v0 = __shfl_sync(0xffffffffu, s[mt][ks][0], src0);
                float v1 = __shfl_sync(0xffffffffu, s[mt][ks][1], src0);
                float v2 = __shfl_sync(0xffffffffu, s[mt][ks][2], src0);
                float v3 = __shfl_sync(0xffffffffu, s[mt][ks][3], src0);
                float w0 = __shfl_sync(0xffffffffu, s[mt][ks][0], src1);
                float w1 = __shfl_sync(0xffffffffu, s[mt][ks][1], src1);
                float w2 = __shfl_sync(0xffffffffu, s[mt][ks][2], src1);
                float w3 = __shfl_sync(0xffffffffu, s[mt][ks][3], src1);
                uint32_t* a = mt ? a1 : a0;
                a[0] = __float_as_uint(odd ? v1 : v0);
                a[1] = __float_as_uint(odd ? v3 : v2);
                a[2] = __float_as_uint(odd ? w1 : w0);
                a[3] = __float_as_uint(odd ? w3 : w2);
            }
#pragma unroll
            for (int nt = 0; nt < 8; nt++) {
                uint32_t b[2];
                b[0] = __float_as_uint(Vs[cur][8 * ks + tig][8 * nt + grp]);
                b[1] = __float_as_uint(Vs[cur][8 * ks + tig + 4][8 * nt + grp]);
                mma_tf32(acc[0][nt], a0, b);
                mma_tf32(acc[1][nt], a1, b);
            }
        }
        __syncthreads();
    }

#pragma unroll
    for (int mt = 0; mt < 2; mt++) {
        float l0 = l[mt][0], l1 = l[mt][1];
        l0 += __shfl_xor_sync(0xffffffffu, l0, 1);
        l0 += __shfl_xor_sync(0xffffffffu, l0, 2);
        l1 += __shfl_xor_sync(0xffffffffu, l1, 1);
        l1 += __shfl_xor_sync(0xffffffffu, l1, 2);
        const float i0 = 1.f / l0, i1 = 1.f / l1;

        const int tq0 = qb * 128 + wm0 + 16 * mt + grp;
        float* o0 = g_O + (size_t)tq0 * DM + h * HD;
        float* o1 = o0 + (size_t)8 * DM;
#pragma unroll
        for (int nt = 0; nt < 8; nt++) {
            const int c  = 8 * nt + 2 * tig;
            const int p0 = (c & ~15) | perm16(c & 15);  // perm(c+1) = p0+4
            o0[p0]     = f2tf32(acc[mt][nt][0] * i0);
            o0[p0 + 4] = f2tf32(acc[mt][nt][1] * i0);
            o1[p0]     = f2tf32(acc[mt][nt][2] * i1);
            o1[p0 + 4] = f2tf32(acc[mt][nt][3] * i1);
        }
    }
}

// ---------------------------------------------------------------------------
extern "C" void kernel_launch(void* const* d_in, const int* in_sizes, int n_in,
                              void* d_out, int out_size)
{
    const float* x     = (const float*)d_in[0];
    const float* freqs = (const float*)d_in[1];
    const float* Wq    = (const float*)d_in[3];
    const float* Wk    = (const float*)d_in[4];
    const float* Wv    = (const float*)d_in[5];
    const float* Wo    = (const float*)d_in[6];
    float* out = (float*)d_out;

    conv_x<<<TT * DM / (256 * 16), 256>>>(x);
    conv_wall<<<dim3(160, 64), 256>>>(Wq, Wk, Wv, Wo);

    gemm_tc<true><<<dim3(3072 / 128, TT / 128), 128>>>(nullptr, freqs);
    attn_tc_kernel<<<dim3(NH, TT / 128), dim3(128)>>>();
    gemm_tc<false><<<dim3(DM / 128, TT / 128), 128>>>(out, nullptr);
}

// round 14
// speedup vs baseline: 1.1062x; 1.1062x over previous
#include <cuda_runtime.h>
#include <math.h>
#include <stdint.h>

#define TT   2048
#define DM   2048
#define NH   32
#define NKV  8
#define HD   64

// ---------------- scratch ----------------
// k of X / O / W permuted within 16-groups: phys = 4*(j&3)+2*((j>>3)&1)+((j>>2)&1)
__device__ float g_X[TT * DM];          // x, tf32, k-permuted
__device__ float g_WT[5120 * DM];       // [n][k] transposed+permuted tf32
__device__ float g_Q[TT * DM];          // RoPE'd, tf32, logical
__device__ float g_K[NKV * TT * HD];    // RoPE'd, tf32, logical
__device__ float g_V[NKV * TT * HD];    // tf32, logical
__device__ float g_O[TT * DM];          // attn out, tf32, k-permuted

__device__ __forceinline__ int perm16(int j) {
    return 4 * (j & 3) + 2 * ((j >> 3) & 1) + ((j >> 2) & 1);
}
__device__ __forceinline__ float f2tf32(float x) {
    float y; asm("cvt.rna.tf32.f32 %0, %1;" : "=f"(y) : "f"(x)); return y;
}
__device__ __forceinline__ void mma_tf32(float* d, const uint32_t* a, const uint32_t* b) {
    asm volatile(
        "mma.sync.aligned.m16n8k8.row.col.f32.tf32.tf32.f32 "
        "{%0,%1,%2,%3}, {%4,%5,%6,%7}, {%8,%9}, {%0,%1,%2,%3};"
        : "+f"(d[0]), "+f"(d[1]), "+f"(d[2]), "+f"(d[3])
        : "r"(a[0]), "r"(a[1]), "r"(a[2]), "r"(a[3]), "r"(b[0]), "r"(b[1]));
}
__device__ __forceinline__ uint32_t smem_u32(const void* p) {
    uint32_t a;
    asm("{ .reg .u64 t; cvta.to.shared.u64 t, %1; cvt.u32.u64 %0, t; }" : "=r"(a) : "l"(p));
    return a;
}
#define CPA16(dst, src) asm volatile("cp.async.cg.shared.global [%0], [%1], 16;" :: "r"(dst), "l"(src))
#define CP_COMMIT()     asm volatile("cp.async.commit_group;" ::: "memory")
#define CP_WAIT(n)      asm volatile("cp.async.wait_group %0;" :: "n"(n) : "memory")

#define GEMM_CTAS 296

// ---------------------------------------------------------------------------
// Pre-pass A: x -> g_X, tf32 + k-perm within 16-groups.
// ---------------------------------------------------------------------------
__global__ __launch_bounds__(256)
void conv_x(const float* __restrict__ src)
{
    const size_t base = ((size_t)blockIdx.x * 256 + threadIdx.x) * 16;
    float4 v0 = *(const float4*)(src + base + 0);
    float4 v1 = *(const float4*)(src + base + 4);
    float4 v2 = *(const float4*)(src + base + 8);
    float4 v3 = *(const float4*)(src + base + 12);
    float4 o;
    o = make_float4(f2tf32(v0.x), f2tf32(v1.x), f2tf32(v2.x), f2tf32(v3.x));
    *(float4*)(g_X + base + 0) = o;
    o = make_float4(f2tf32(v0.y), f2tf32(v1.y), f2tf32(v2.y), f2tf32(v3.y));
    *(float4*)(g_X + base + 4) = o;
    o = make_float4(f2tf32(v0.z), f2tf32(v1.z), f2tf32(v2.z), f2tf32(v3.z));
    *(float4*)(g_X + base + 8) = o;
    o = make_float4(f2tf32(v0.w), f2tf32(v1.w), f2tf32(v2.w), f2tf32(v3.w));
    *(float4*)(g_X + base + 12) = o;
}

// ---------------------------------------------------------------------------
// Pre-pass B (fused): all 4 weights -> g_WT, transposed + tf32 + k-perm.
// ---------------------------------------------------------------------------
__global__ __launch_bounds__(256)
void conv_wall(const float* __restrict__ Wq, const float* __restrict__ Wk,
               const float* __restrict__ Wv, const float* __restrict__ Wo)
{
    __shared__ float tile[32][33];
    const int bx = blockIdx.x;
    const float* src; int N, rowbase, n0;
    if (bx < 64)      { src = Wq; N = 2048; rowbase = 0;    n0 = bx * 32; }
    else if (bx < 80) { src = Wk; N = 512;  rowbase = 2048; n0 = (bx - 64) * 32; }
    else if (bx < 96) { src = Wv; N = 512;  rowbase = 2560; n0 = (bx - 80) * 32; }
    else              { src = Wo; N = 2048; rowbase = 3072; n0 = (bx - 96) * 32; }

    const int tx = threadIdx.x & 31, ty = threadIdx.x >> 5;
    const int k0 = blockIdx.y * 32;
#pragma unroll
    for (int i = 0; i < 4; i++)
        tile[ty + 8 * i][tx] = src[(size_t)(k0 + ty + 8 * i) * N + n0 + tx];
    __syncthreads();
    const int pk = (tx & 16) | perm16(tx & 15);
#pragma unroll
    for (int i = 0; i < 4; i++) {
        const int nl = ty + 8 * i;
        g_WT[(size_t)(rowbase + n0 + nl) * DM + k0 + pk] = f2tf32(tile[tx][nl]);
    }
}

// ---------------------------------------------------------------------------
// TF32 GEMM (R11 body), PERSISTENT: 296 CTAs stride over 128x128 tiles.
// 8 warps, 64x32 warp tiles, 2-stage cp.async, LDS.128 fragments.
// ---------------------------------------------------------------------------
template <bool QKV>
__global__ __launch_bounds__(256)
void gemm_tc(float* __restrict__ Cout, const float* __restrict__ freqs)
{
    __shared__ __align__(16) float As[2][128][32];
    __shared__ __align__(16) float Bs[2][128][32];

    const int tid  = threadIdx.x;
    const int lane = tid & 31;
    const int warp = tid >> 5;
    const int wm0  = (warp & 1) * 64;
    const int wn0  = (warp >> 1) * 32;
    const int grp  = lane >> 2;
    const int tig  = lane & 3;

    const int ncols  = QKV ? 24 : 16;            // col-tiles
    const int ntiles = ncols * 16;               // x 16 row-tiles

    const float* A = QKV ? g_X : g_O;

    const uint32_t aBase = smem_u32(&As[0][0][0]);
    const uint32_t bBase = smem_u32(&Bs[0][0][0]);

    const int st = tid & 7;
    const int par = (grp & 1) << 2;

    for (int t = blockIdx.x; t < ntiles; t += GEMM_CTAS) {
        const int row0  = (t / ncols) * 128;
        const int col0g = (t % ncols) * 128;

        const float* Aptr = A + (size_t)row0 * DM + st * 4;
        const float* Bptr = g_WT + (size_t)((QKV ? 0 : 3072) + col0g) * DM + st * 4;

#define STAGE(buf, k0)                                                        \
    {                                                                         \
        _Pragma("unroll")                                                     \
        for (int it = 0; it < 4; it++) {                                      \
            const int rw = it * 32 + (tid >> 3);                              \
            const uint32_t doff = (uint32_t)(buf) * 16384u + rw * 128u +      \
                                  ((uint32_t)(st ^ ((rw & 1) << 2))) * 16u;   \
            CPA16(aBase + doff, Aptr + (size_t)rw * DM + (k0));               \
            CPA16(bBase + doff, Bptr + (size_t)rw * DM + (k0));               \
        }                                                                     \
    }

        STAGE(0, 0);
        CP_COMMIT();

        float acc[4][4][4];
#pragma unroll
        for (int mt = 0; mt < 4; mt++)
#pragma unroll
            for (int nt = 0; nt < 4; nt++)
#pragma unroll
                for (int u = 0; u < 4; u++) acc[mt][nt][u] = 0.f;

        for (int s = 0; s < 64; s++) {
            const int cur = s & 1;
            if (s + 1 < 64) {
                STAGE((s + 1) & 1, (s + 1) * 32);
                CP_COMMIT();
                CP_WAIT(1);
            } else {
                CP_WAIT(0);
            }
            __syncthreads();

#pragma unroll
            for (int c = 0; c < 2; c++) {
                const int q = (((c << 2) + tig) ^ par) << 2;
                float4 Bf[4];
#pragma unroll
                for (int nt = 0; nt < 4; nt++)
                    Bf[nt] = *(const float4*)&Bs[cur][wn0 + nt * 8 + grp][q];
#pragma unroll
                for (int mt = 0; mt < 4; mt++) {
                    const int r = wm0 + mt * 16 + grp;
                    float4 A0 = *(const float4*)&As[cur][r][q];
                    float4 A1 = *(const float4*)&As[cur][r + 8][q];
                    uint32_t ae[4] = {__float_as_uint(A0.x), __float_as_uint(A1.x),
                                      __float_as_uint(A0.y), __float_as_uint(A1.y)};
                    uint32_t ao[4] = {__float_as_uint(A0.z), __float_as_uint(A1.z),
                                      __float_as_uint(A0.w), __float_as_uint(A1.w)};
#pragma unroll
                    for (int nt = 0; nt < 4; nt++) {
                        uint32_t be[2] = {__float_as_uint(Bf[nt].x), __float_as_uint(Bf[nt].y)};
                        mma_tf32(acc[mt][nt], ae, be);
                    }
#pragma unroll
                    for (int nt = 0; nt < 4; nt++) {
                        uint32_t bo[2] = {__float_as_uint(Bf[nt].z), __float_as_uint(Bf[nt].w)};
                        mma_tf32(acc[mt][nt], ao, bo);
                    }
                }
            }
            __syncthreads();
        }
#undef STAGE

        // epilogue
#pragma unroll
        for (int mt = 0; mt < 4; mt++) {
#pragma unroll
            for (int nt = 0; nt < 4; nt++) {
                const int rb = row0 + wm0 + mt * 16 + grp;
                const int cb = col0g + wn0 + nt * 8 + tig * 2;
#pragma unroll
                for (int half = 0; half < 2; half++) {
                    const int r = rb + half * 8;
                    const float v0 = acc[mt][nt][half * 2 + 0];
                    const float v1 = acc[mt][nt][half * 2 + 1];
                    if (!QKV) {
                        *(float2*)(Cout + (size_t)r * DM + cb) = make_float2(v0, v1);
                    } else if (cb >= 2560) {   // V
                        const int lc = cb - 2560;
                        const int kv = lc >> 6, d = lc & 63;
                        *(float2*)(g_V + ((size_t)kv * TT + r) * HD + d) =
                            make_float2(f2tf32(v0), f2tf32(v1));
                    } else {                   // Q or K: RoPE (logical layout)
                        const int lc = (cb >= 2048) ? cb - 2048 : cb;
                        const int d = lc & 63;
                        const float cs = freqs[(size_t)r * HD + d];
                        const float sn = freqs[(size_t)TT * HD + (size_t)r * HD + d];
                        const float o0 = f2tf32(v0 * cs - v1 * sn);
                        const float o1 = f2tf32(v1 * cs + v0 * sn);
                        if (cb < 2048) {
                            *(float2*)(g_Q + (size_t)r * DM + cb) = make_float2(o0, o1);
                        } else {
                            const int kv = lc >> 6;
                            *(float2*)(g_K + ((size_t)kv * TT + r) * HD + d) = make_float2(o0, o1);
                        }
                    }
                }
            }
        }
    }
}

// ---------------------------------------------------------------------------
// Tensor-core flash attention (R11-exact), mt=2: CTA = 128 queries x 1 head.
// ---------------------------------------------------------------------------
__global__ __launch_bounds__(128, 2)
void attn_tc_kernel()
{
    __shared__ __align__(16) float Ks[2][64][68];
    __shared__ __align__(16) float Vs[2][64][68];

    const int h   = blockIdx.x;
    const int qb  = (TT / 128 - 1) - blockIdx.y;   // heavy first
    const int kvh = h >> 2;
    const int tid  = threadIdx.x;
    const int lane = tid & 31;
    const int warp = tid >> 5;
    const int wm0  = warp * 32;
    const int grp  = lane >> 2;
    const int tig  = lane & 3;

    const float* kbase = g_K + (size_t)kvh * TT * HD;
    const float* vbase = g_V + (size_t)kvh * TT * HD;

    {
        const float* qsrc = g_Q + ((size_t)(qb * 128)) * DM + h * HD;
#pragma unroll
        for (int i = 0; i < 8; i++) {
            const int j = i * 128 + tid;
            const int row = j >> 4, c4 = (j & 15) * 4;
            float4 v = *(const float4*)(qsrc + (size_t)row * DM + c4);
            Ks[0][row][c4 + 0] = v.x * 0.125f;
            Ks[0][row][c4 + 1] = v.y * 0.125f;
            Ks[0][row][c4 + 2] = v.z * 0.125f;
            Ks[0][row][c4 + 3] = v.w * 0.125f;
            float4 w = *(const float4*)(qsrc + (size_t)(row + 64) * DM + c4);
            Vs[0][row][c4 + 0] = w.x * 0.125f;
            Vs[0][row][c4 + 1] = w.y * 0.125f;
            Vs[0][row][c4 + 2] = w.z * 0.125f;
            Vs[0][row][c4 + 3] = w.w * 0.125f;
        }
    }
    __syncthreads();

    uint32_t qf[2][8][4];
#pragma unroll
    for (int mt = 0; mt < 2; mt++) {
        const int rg = wm0 + 16 * mt;
        const float (*Qt)[68] = (rg < 64) ? Ks[0] : Vs[0];
        const int rb = rg & 63;
#pragma unroll
        for (int ks = 0; ks < 8; ks++) {
            qf[mt][ks][0] = __float_as_uint(Qt[rb + grp][8 * ks + tig]);
            qf[mt][ks][1] = __float_as_uint(Qt[rb + grp + 8][8 * ks + tig]);
            qf[mt][ks][2] = __float_as_uint(Qt[rb + grp][8 * ks + tig + 4]);
            qf[mt][ks][3] = __float_as_uint(Qt[rb + grp + 8][8 * ks + tig + 4]);
        }
    }
    __syncthreads();

    const int krow = tid >> 4;
    const int kc4  = (tid & 15) * 4;
    const uint32_t kDst = smem_u32(&Ks[0][krow][kc4]);
    const uint32_t vDst = smem_u32(&Vs[0][krow][kc4]);
    const uint32_t bufStride = 64 * 68 * 4;
    const float* kSrc = kbase + (size_t)krow * HD + kc4;
    const float* vSrc = vbase + (size_t)krow * HD + kc4;

#pragma unroll
    for (int i = 0; i < 8; i++) CPA16(kDst + i * 8 * 272, kSrc + (size_t)(8 * i) * HD);
#pragma unroll
    for (int i = 0; i < 8; i++) CPA16(vDst + i * 8 * 272, vSrc + (size_t)(8 * i) * HD);
    CP_COMMIT();

    float acc[2][8][4];
#pragma unroll
    for (int mt = 0; mt < 2; mt++)
#pragma unroll
        for (int nt = 0; nt < 8; nt++)
#pragma unroll
            for (int u = 0; u < 4; u++) acc[mt][nt][u] = 0.f;
    float m[2][2] = {{-1e30f, -1e30f}, {-1e30f, -1e30f}};
    float l[2][2] = {{0.f, 0.f}, {0.f, 0.f}};

    const int src0 = (lane & ~3) + (tig >> 1);
    const int src1 = src0 + 2;
    const bool odd = tig & 1;

    const int ntiles = 2 * qb + 2;

    for (int kt = 0; kt < ntiles; kt++) {
        const int cur = kt & 1;
        if (kt + 1 < ntiles) {
            const int nb = (kt + 1) & 1;
            const size_t off = (size_t)(kt + 1) * 64 * HD;
#pragma unroll
            for (int i = 0; i < 8; i++)
                CPA16(kDst + nb * bufStride + i * 8 * 272, kSrc + off + (size_t)(8 * i) * HD);
#pragma unroll
            for (int i = 0; i < 8; i++)
                CPA16(vDst + nb * bufStride + i * 8 * 272, vSrc + off + (size_t)(8 * i) * HD);
            CP_COMMIT();
            CP_WAIT(1);
        } else {
            CP_WAIT(0);
        }
        __syncthreads();

        float s[2][8][4];
#pragma unroll
        for (int mt = 0; mt < 2; mt++)
#pragma unroll
            for (int nt = 0; nt < 8; nt++)
#pragma unroll
                for (int u = 0; u < 4; u++) s[mt][nt][u] = 0.f;

#pragma unroll
        for (int ks = 0; ks < 8; ks++) {
#pragma unroll
            for (int nt = 0; nt < 8; nt++) {
                uint32_t b[2];
                b[0] = __float_as_uint(Ks[cur][8 * nt + grp][8 * ks + tig]);
                b[1] = __float_as_uint(Ks[cur][8 * nt + grp][8 * ks + tig + 4]);
                mma_tf32(s[0][nt], qf[0][ks], b);
                mma_tf32(s[1][nt], qf[1][ks], b);
            }
        }

        if (kt >= 2 * qb) {
#pragma unroll
            for (int mt = 0; mt < 2; mt++) {
                const int r0 = 128 * qb + wm0 + 16 * mt + grp;
                const int r1 = r0 + 8;
#pragma unroll
                for (int nt = 0; nt < 8; nt++) {
                    const int c = 64 * kt + 8 * nt + 2 * tig;
                    if (c > r0)     s[mt][nt][0] = -1e30f;
                    if (c + 1 > r0) s[mt][nt][1] = -1e30f;
                    if (c > r1)     s[mt][nt][2] = -1e30f;
                    if (c + 1 > r1) s[mt][nt][3] = -1e30f;
                }
            }
        }

#pragma unroll
        for (int mt = 0; mt < 2; mt++) {
            float t0 = -1e30f, t1 = -1e30f;
#pragma unroll
            for (int nt = 0; nt < 8; nt++) {
                t0 = fmaxf(t0, fmaxf(s[mt][nt][0], s[mt][nt][1]));
                t1 = fmaxf(t1, fmaxf(s[mt][nt][2], s[mt][nt][3]));
            }
            t0 = fmaxf(t0, __shfl_xor_sync(0xffffffffu, t0, 1));
            t0 = fmaxf(t0, __shfl_xor_sync(0xffffffffu, t0, 2));
            t1 = fmaxf(t1, __shfl_xor_sync(0xffffffffu, t1, 1));
            t1 = fmaxf(t1, __shfl_xor_sync(0xffffffffu, t1, 2));

            const float mn0 = fmaxf(m[mt][0], t0), mn1 = fmaxf(m[mt][1], t1);
            const float cr0 = __expf(m[mt][0] - mn0), cr1 = __expf(m[mt][1] - mn1);
            m[mt][0] = mn0; m[mt][1] = mn1;
            l[mt][0] *= cr0; l[mt][1] *= cr1;
#pragma unroll
            for (int nt = 0; nt < 8; nt++) {
                acc[mt][nt][0] *= cr0; acc[mt][nt][1] *= cr0;
                acc[mt][nt][2] *= cr1; acc[mt][nt][3] *= cr1;
            }
#pragma unroll
            for (int nt = 0; nt < 8; nt++) {
                float p0 = f2tf32(__expf(s[mt][nt][0] - mn0));
                float p1 = f2tf32(__expf(s[mt][nt][1] - mn0));
                float p2 = f2tf32(__expf(s[mt][nt][2] - mn1));
                float p3 = f2tf32(__expf(s[mt][nt][3] - mn1));
                l[mt][0] += p0 + p1; l[mt][1] += p2 + p3;
                s[mt][nt][0] = p0; s[mt][nt][1] = p1; s[mt][nt][2] = p2; s[mt][nt][3] = p3;
            }
        }

#pragma unroll
        for (int ks = 0; ks < 8; ks++) {
            uint32_t a0[4], a1[4];
#pragma unroll
            for (int mt = 0; mt < 2; mt++) {
                float v0 = __shfl_sync(0xffffffffu, s[mt][ks][0], src0);
                float v1 = __shfl_sync(0xffffffffu, s[mt][ks][1], src0);
                float v2 = __shfl_sync(0xffffffffu, s[mt][ks][2], src0);
                float v3 = __shfl_sync(0xffffffffu, s[mt][ks][3], src0);
                float w0 = __shfl_sync(0xffffffffu, s[mt][ks][0], src1);
                float w1 = __shfl_sync(0xffffffffu, s[mt][ks][1], src1);
                float w2 = __shfl_sync(0xffffffffu, s[mt][ks][2], src1);
                float w3 = __shfl_sync(0xffffffffu, s[mt][ks][3], src1);
                uint32_t* a = mt ? a1 : a0;
                a[0] = __float_as_uint(odd ? v1 : v0);
                a[1] = __float_as_uint(odd ? v3 : v2);
                a[2] = __float_as_uint(odd ? w1 : w0);
                a[3] = __float_as_uint(odd ? w3 : w2);
            }
#pragma unroll
            for (int nt = 0; nt < 8; nt++) {
                uint32_t b[2];
                b[0] = __float_as_uint(Vs[cur][8 * ks + tig][8 * nt + grp]);
                b[1] = __float_as_uint(Vs[cur][8 * ks + tig + 4][8 * nt + grp]);
                mma_tf32(acc[0][nt], a0, b);
                mma_tf32(acc[1][nt], a1, b);
            }
        }
        __syncthreads();
    }

#pragma unroll
    for (int mt = 0; mt < 2; mt++) {
        float l0 = l[mt][0], l1 = l[mt][1];
        l0 += __shfl_xor_sync(0xffffffffu, l0, 1);
        l0 += __shfl_xor_sync(0xffffffffu, l0, 2);
        l1 += __shfl_xor_sync(0xffffffffu, l1, 1);
        l1 += __shfl_xor_sync(0xffffffffu, l1, 2);
        const float i0 = 1.f / l0, i1 = 1.f / l1;

        const int tq0 = qb * 128 + wm0 + 16 * mt + grp;
        float* o0 = g_O + (size_t)tq0 * DM + h * HD;
        float* o1 = o0 + (size_t)8 * DM;
#pragma unroll
        for (int nt = 0; nt < 8; nt++) {
            const int c  = 8 * nt + 2 * tig;
            const int p0 = (c & ~15) | perm16(c & 15);  // perm(c+1) = p0+4
            o0[p0]     = f2tf32(acc[mt][nt][0] * i0);
            o0[p0 + 4] = f2tf32(acc[mt][nt][1] * i0);
            o1[p0]     = f2tf32(acc[mt][nt][2] * i1);
            o1[p0 + 4] = f2tf32(acc[mt][nt][3] * i1);
        }
    }
}

// ---------------------------------------------------------------------------
extern "C" void kernel_launch(void* const* d_in, const int* in_sizes, int n_in,
                              void* d_out, int out_size)
{
    const float* x     = (const float*)d_in[0];
    const float* freqs = (const float*)d_in[1];
    const float* Wq    = (const float*)d_in[3];
    const float* Wk    = (const float*)d_in[4];
    const float* Wv    = (const float*)d_in[5];
    const float* Wo    = (const float*)d_in[6];
    float* out = (float*)d_out;

    conv_x<<<TT * DM / (256 * 16), 256>>>(x);
    conv_wall<<<dim3(160, 64), 256>>>(Wq, Wk, Wv, Wo);

    gemm_tc<true><<<GEMM_CTAS, 256>>>(nullptr, freqs);     // persistent QKV (+RoPE)
    attn_tc_kernel<<<dim3(NH, TT / 128), dim3(128)>>>();
    gemm_tc<false><<<GEMM_CTAS, 256>>>(out, nullptr);      // persistent O-proj
}

// round 15
// speedup vs baseline: 1.1082x; 1.0018x over previous
#include <cuda_runtime.h>
#include <math.h>
#include <stdint.h>

#define TT   2048
#define DM   2048
#define NH   32
#define NKV  8
#define HD   64

// ---------------- scratch ----------------
// k of X / O / W permuted within 16-groups: phys = 4*(j&3)+2*((j>>3)&1)+((j>>2)&1)
__device__ float g_X[TT * DM];          // x, tf32, k-permuted
__device__ float g_WT[5120 * DM];       // [n][k] transposed+permuted tf32
__device__ float g_Q[TT * DM];          // RoPE'd, tf32, logical
__device__ float g_K[NKV * TT * HD];    // RoPE'd, tf32, logical
__device__ float g_V[NKV * TT * HD];    // tf32, logical
__device__ float g_O[TT * DM];          // attn out, tf32, k-permuted

__device__ __forceinline__ int perm16(int j) {
    return 4 * (j & 3) + 2 * ((j >> 3) & 1) + ((j >> 2) & 1);
}
__device__ __forceinline__ float f2tf32(float x) {
    float y; asm("cvt.rna.tf32.f32 %0, %1;" : "=f"(y) : "f"(x)); return y;
}
__device__ __forceinline__ float fexp2(float x) {
    float y; asm("ex2.approx.f32 %0, %1;" : "=f"(y) : "f"(x)); return y;
}
__device__ __forceinline__ void mma_tf32(float* d, const uint32_t* a, const uint32_t* b) {
    asm volatile(
        "mma.sync.aligned.m16n8k8.row.col.f32.tf32.tf32.f32 "
        "{%0,%1,%2,%3}, {%4,%5,%6,%7}, {%8,%9}, {%0,%1,%2,%3};"
        : "+f"(d[0]), "+f"(d[1]), "+f"(d[2]), "+f"(d[3])
        : "r"(a[0]), "r"(a[1]), "r"(a[2]), "r"(a[3]), "r"(b[0]), "r"(b[1]));
}
__device__ __forceinline__ uint32_t smem_u32(const void* p) {
    uint32_t a;
    asm("{ .reg .u64 t; cvta.to.shared.u64 t, %1; cvt.u32.u64 %0, t; }" : "=r"(a) : "l"(p));
    return a;
}
#define CPA16(dst, src) asm volatile("cp.async.cg.shared.global [%0], [%1], 16;" :: "r"(dst), "l"(src))
#define CP_COMMIT()     asm volatile("cp.async.commit_group;" ::: "memory")
#define CP_WAIT(n)      asm volatile("cp.async.wait_group %0;" :: "n"(n) : "memory")

#define GEMM_CTAS 296

// ---------------------------------------------------------------------------
// Pre-pass (single launch): weights -> g_WT (transpose+tf32+perm), x -> g_X.
// grid (176, 64): bx<64 Wq | <80 Wk | <96 Wv | <160 Wo | <176 x-chunks
// ---------------------------------------------------------------------------
__global__ __launch_bounds__(256)
void conv_all(const float* __restrict__ x,
              const float* __restrict__ Wq, const float* __restrict__ Wk,
              const float* __restrict__ Wv, const float* __restrict__ Wo)
{
    const int bx = blockIdx.x;
    if (bx >= 160) {
        // x conversion: 1024 logical blocks = (bx-160)*64 + by
        const int blk = (bx - 160) * 64 + blockIdx.y;
        const size_t base = ((size_t)blk * 256 + threadIdx.x) * 16;
        float4 v0 = *(const float4*)(x + base + 0);
        float4 v1 = *(const float4*)(x + base + 4);
        float4 v2 = *(const float4*)(x + base + 8);
        float4 v3 = *(const float4*)(x + base + 12);
        float4 o;
        o = make_float4(f2tf32(v0.x), f2tf32(v1.x), f2tf32(v2.x), f2tf32(v3.x));
        *(float4*)(g_X + base + 0) = o;
        o = make_float4(f2tf32(v0.y), f2tf32(v1.y), f2tf32(v2.y), f2tf32(v3.y));
        *(float4*)(g_X + base + 4) = o;
        o = make_float4(f2tf32(v0.z), f2tf32(v1.z), f2tf32(v2.z), f2tf32(v3.z));
        *(float4*)(g_X + base + 8) = o;
        o = make_float4(f2tf32(v0.w), f2tf32(v1.w), f2tf32(v2.w), f2tf32(v3.w));
        *(float4*)(g_X + base + 12) = o;
        return;
    }

    __shared__ float tile[32][33];
    const float* src; int N, rowbase, n0;
    if (bx < 64)      { src = Wq; N = 2048; rowbase = 0;    n0 = bx * 32; }
    else if (bx < 80) { src = Wk; N = 512;  rowbase = 2048; n0 = (bx - 64) * 32; }
    else if (bx < 96) { src = Wv; N = 512;  rowbase = 2560; n0 = (bx - 80) * 32; }
    else              { src = Wo; N = 2048; rowbase = 3072; n0 = (bx - 96) * 32; }

    const int tx = threadIdx.x & 31, ty = threadIdx.x >> 5;
    const int k0 = blockIdx.y * 32;
#pragma unroll
    for (int i = 0; i < 4; i++)
        tile[ty + 8 * i][tx] = src[(size_t)(k0 + ty + 8 * i) * N + n0 + tx];
    __syncthreads();
    const int pk = (tx & 16) | perm16(tx & 15);
#pragma unroll
    for (int i = 0; i < 4; i++) {
        const int nl = ty + 8 * i;
        g_WT[(size_t)(rowbase + n0 + nl) * DM + k0 + pk] = f2tf32(tile[tx][nl]);
    }
}

// ---------------------------------------------------------------------------
// TF32 GEMM (R14): PERSISTENT, 296 CTAs stride over 128x128 tiles.
// 8 warps, 64x32 warp tiles, 2-stage cp.async, LDS.128 fragments.
// ---------------------------------------------------------------------------
template <bool QKV>
__global__ __launch_bounds__(256)
void gemm_tc(float* __restrict__ Cout, const float* __restrict__ freqs)
{
    __shared__ __align__(16) float As[2][128][32];
    __shared__ __align__(16) float Bs[2][128][32];

    const int tid  = threadIdx.x;
    const int lane = tid & 31;
    const int warp = tid >> 5;
    const int wm0  = (warp & 1) * 64;
    const int wn0  = (warp >> 1) * 32;
    const int grp  = lane >> 2;
    const int tig  = lane & 3;

    const int ncols  = QKV ? 24 : 16;
    const int ntiles = ncols * 16;

    const float* A = QKV ? g_X : g_O;

    const uint32_t aBase = smem_u32(&As[0][0][0]);
    const uint32_t bBase = smem_u32(&Bs[0][0][0]);

    const int st = tid & 7;
    const int par = (grp & 1) << 2;

    for (int t = blockIdx.x; t < ntiles; t += GEMM_CTAS) {
        const int row0  = (t / ncols) * 128;
        const int col0g = (t % ncols) * 128;

        const float* Aptr = A + (size_t)row0 * DM + st * 4;
        const float* Bptr = g_WT + (size_t)((QKV ? 0 : 3072) + col0g) * DM + st * 4;

#define STAGE(buf, k0)                                                        \
    {                                                                         \
        _Pragma("unroll")                                                     \
        for (int it = 0; it < 4; it++) {                                      \
            const int rw = it * 32 + (tid >> 3);                              \
            const uint32_t doff = (uint32_t)(buf) * 16384u + rw * 128u +      \
                                  ((uint32_t)(st ^ ((rw & 1) << 2))) * 16u;   \
            CPA16(aBase + doff, Aptr + (size_t)rw * DM + (k0));               \
            CPA16(bBase + doff, Bptr + (size_t)rw * DM + (k0));               \
        }                                                                     \
    }

        STAGE(0, 0);
        CP_COMMIT();

        float acc[4][4][4];
#pragma unroll
        for (int mt = 0; mt < 4; mt++)
#pragma unroll
            for (int nt = 0; nt < 4; nt++)
#pragma unroll
                for (int u = 0; u < 4; u++) acc[mt][nt][u] = 0.f;

        for (int s = 0; s < 64; s++) {
            const int cur = s & 1;
            if (s + 1 < 64) {
                STAGE((s + 1) & 1, (s + 1) * 32);
                CP_COMMIT();
                CP_WAIT(1);
            } else {
                CP_WAIT(0);
            }
            __syncthreads();

#pragma unroll
            for (int c = 0; c < 2; c++) {
                const int q = (((c << 2) + tig) ^ par) << 2;
                float4 Bf[4];
#pragma unroll
                for (int nt = 0; nt < 4; nt++)
                    Bf[nt] = *(const float4*)&Bs[cur][wn0 + nt * 8 + grp][q];
#pragma unroll
                for (int mt = 0; mt < 4; mt++) {
                    const int r = wm0 + mt * 16 + grp;
                    float4 A0 = *(const float4*)&As[cur][r][q];
                    float4 A1 = *(const float4*)&As[cur][r + 8][q];
                    uint32_t ae[4] = {__float_as_uint(A0.x), __float_as_uint(A1.x),
                                      __float_as_uint(A0.y), __float_as_uint(A1.y)};
                    uint32_t ao[4] = {__float_as_uint(A0.z), __float_as_uint(A1.z),
                                      __float_as_uint(A0.w), __float_as_uint(A1.w)};
#pragma unroll
                    for (int nt = 0; nt < 4; nt++) {
                        uint32_t be[2] = {__float_as_uint(Bf[nt].x), __float_as_uint(Bf[nt].y)};
                        mma_tf32(acc[mt][nt], ae, be);
                    }
#pragma unroll
                    for (int nt = 0; nt < 4; nt++) {
                        uint32_t bo[2] = {__float_as_uint(Bf[nt].z), __float_as_uint(Bf[nt].w)};
                        mma_tf32(acc[mt][nt], ao, bo);
                    }
                }
            }
            __syncthreads();
        }
#undef STAGE

#pragma unroll
        for (int mt = 0; mt < 4; mt++) {
#pragma unroll
            for (int nt = 0; nt < 4; nt++) {
                const int rb = row0 + wm0 + mt * 16 + grp;
                const int cb = col0g + wn0 + nt * 8 + tig * 2;
#pragma unroll
                for (int half = 0; half < 2; half++) {
                    const int r = rb + half * 8;
                    const float v0 = acc[mt][nt][half * 2 + 0];
                    const float v1 = acc[mt][nt][half * 2 + 1];
                    if (!QKV) {
                        *(float2*)(Cout + (size_t)r * DM + cb) = make_float2(v0, v1);
                    } else if (cb >= 2560) {   // V
                        const int lc = cb - 2560;
                        const int kv = lc >> 6, d = lc & 63;
                        *(float2*)(g_V + ((size_t)kv * TT + r) * HD + d) =
                            make_float2(f2tf32(v0), f2tf32(v1));
                    } else {                   // Q or K: RoPE (logical layout)
                        const int lc = (cb >= 2048) ? cb - 2048 : cb;
                        const int d = lc & 63;
                        const float cs = freqs[(size_t)r * HD + d];
                        const float sn = freqs[(size_t)TT * HD + (size_t)r * HD + d];
                        const float o0 = f2tf32(v0 * cs - v1 * sn);
                        const float o1 = f2tf32(v1 * cs + v0 * sn);
                        if (cb < 2048) {
                            *(float2*)(g_Q + (size_t)r * DM + cb) = make_float2(o0, o1);
                        } else {
                            const int kv = lc >> 6;
                            *(float2*)(g_K + ((size_t)kv * TT + r) * HD + d) = make_float2(o0, o1);
                        }
                    }
                }
            }
        }
    }
}

// ---------------------------------------------------------------------------
// Tensor-core flash attention, mt=2, log2-domain softmax (ex2, no mul),
// full-warp causal skip on the last key tile.
// ---------------------------------------------------------------------------
#define QSCALE 0.180336878f   // 0.125 * log2(e)

__global__ __launch_bounds__(128, 2)
void attn_tc_kernel()
{
    __shared__ __align__(16) float Ks[2][64][68];
    __shared__ __align__(16) float Vs[2][64][68];

    const int h   = blockIdx.x;
    const int qb  = (TT / 128 - 1) - blockIdx.y;   // heavy first
    const int kvh = h >> 2;
    const int tid  = threadIdx.x;
    const int lane = tid & 31;
    const int warp = tid >> 5;
    const int wm0  = warp * 32;
    const int grp  = lane >> 2;
    const int tig  = lane & 3;

    const float* kbase = g_K + (size_t)kvh * TT * HD;
    const float* vbase = g_V + (size_t)kvh * TT * HD;

    // ---- stage Q (x 0.125*log2e, re-rounded tf32) ----
    {
        const float* qsrc = g_Q + ((size_t)(qb * 128)) * DM + h * HD;
#pragma unroll
        for (int i = 0; i < 8; i++) {
            const int j = i * 128 + tid;
            const int row = j >> 4, c4 = (j & 15) * 4;
            float4 v = *(const float4*)(qsrc + (size_t)row * DM + c4);
            Ks[0][row][c4 + 0] = f2tf32(v.x * QSCALE);
            Ks[0][row][c4 + 1] = f2tf32(v.y * QSCALE);
            Ks[0][row][c4 + 2] = f2tf32(v.z * QSCALE);
            Ks[0][row][c4 + 3] = f2tf32(v.w * QSCALE);
            float4 w = *(const float4*)(qsrc + (size_t)(row + 64) * DM + c4);
            Vs[0][row][c4 + 0] = f2tf32(w.x * QSCALE);
            Vs[0][row][c4 + 1] = f2tf32(w.y * QSCALE);
            Vs[0][row][c4 + 2] = f2tf32(w.z * QSCALE);
            Vs[0][row][c4 + 3] = f2tf32(w.w * QSCALE);
        }
    }
    __syncthreads();

    uint32_t qf[2][8][4];
#pragma unroll
    for (int mt = 0; mt < 2; mt++) {
        const int rg = wm0 + 16 * mt;
        const float (*Qt)[68] = (rg < 64) ? Ks[0] : Vs[0];
        const int rb = rg & 63;
#pragma unroll
        for (int ks = 0; ks < 8; ks++) {
            qf[mt][ks][0] = __float_as_uint(Qt[rb + grp][8 * ks + tig]);
            qf[mt][ks][1] = __float_as_uint(Qt[rb + grp + 8][8 * ks + tig]);
            qf[mt][ks][2] = __float_as_uint(Qt[rb + grp][8 * ks + tig + 4]);
            qf[mt][ks][3] = __float_as_uint(Qt[rb + grp + 8][8 * ks + tig + 4]);
        }
    }
    __syncthreads();

    const int krow = tid >> 4;
    const int kc4  = (tid & 15) * 4;
    const uint32_t kDst = smem_u32(&Ks[0][krow][kc4]);
    const uint32_t vDst = smem_u32(&Vs[0][krow][kc4]);
    const uint32_t bufStride = 64 * 68 * 4;
    const float* kSrc = kbase + (size_t)krow * HD + kc4;
    const float* vSrc = vbase + (size_t)krow * HD + kc4;

#pragma unroll
    for (int i = 0; i < 8; i++) CPA16(kDst + i * 8 * 272, kSrc + (size_t)(8 * i) * HD);
#pragma unroll
    for (int i = 0; i < 8; i++) CPA16(vDst + i * 8 * 272, vSrc + (size_t)(8 * i) * HD);
    CP_COMMIT();

    float acc[2][8][4];
#pragma unroll
    for (int mt = 0; mt < 2; mt++)
#pragma unroll
        for (int nt = 0; nt < 8; nt++)
#pragma unroll
            for (int u = 0; u < 4; u++) acc[mt][nt][u] = 0.f;
    float m[2][2] = {{-1e30f, -1e30f}, {-1e30f, -1e30f}};
    float l[2][2] = {{0.f, 0.f}, {0.f, 0.f}};

    const int src0 = (lane & ~3) + (tig >> 1);
    const int src1 = src0 + 2;
    const bool odd = tig & 1;

    const int ntiles = 2 * qb + 2;

    for (int kt = 0; kt < ntiles; kt++) {
        const int cur = kt & 1;
        if (kt + 1 < ntiles) {
            const int nb = (kt + 1) & 1;
            const size_t off = (size_t)(kt + 1) * 64 * HD;
#pragma unroll
            for (int i = 0; i < 8; i++)
                CPA16(kDst + nb * bufStride + i * 8 * 272, kSrc + off + (size_t)(8 * i) * HD);
#pragma unroll
            for (int i = 0; i < 8; i++)
                CPA16(vDst + nb * bufStride + i * 8 * 272, vSrc + off + (size_t)(8 * i) * HD);
            CP_COMMIT();
            CP_WAIT(1);
        } else {
            CP_WAIT(0);
        }
        __syncthreads();

        // full-warp causal skip: last tile, warps 0-1 are entirely masked
        if (!(kt == 2 * qb + 1 && wm0 < 64)) {

        float s[2][8][4];
#pragma unroll
        for (int mt = 0; mt < 2; mt++)
#pragma unroll
            for (int nt = 0; nt < 8; nt++)
#pragma unroll
                for (int u = 0; u < 4; u++) s[mt][nt][u] = 0.f;

#pragma unroll
        for (int ks = 0; ks < 8; ks++) {
#pragma unroll
            for (int nt = 0; nt < 8; nt++) {
                uint32_t b[2];
                b[0] = __float_as_uint(Ks[cur][8 * nt + grp][8 * ks + tig]);
                b[1] = __float_as_uint(Ks[cur][8 * nt + grp][8 * ks + tig + 4]);
                mma_tf32(s[0][nt], qf[0][ks], b);
                mma_tf32(s[1][nt], qf[1][ks], b);
            }
        }

        if (kt >= 2 * qb) {
#pragma unroll
            for (int mt = 0; mt < 2; mt++) {
                const int r0 = 128 * qb + wm0 + 16 * mt + grp;
                const int r1 = r0 + 8;
#pragma unroll
                for (int nt = 0; nt < 8; nt++) {
                    const int c = 64 * kt + 8 * nt + 2 * tig;
                    if (c > r0)     s[mt][nt][0] = -1e30f;
                    if (c + 1 > r0) s[mt][nt][1] = -1e30f;
                    if (c > r1)     s[mt][nt][2] = -1e30f;
                    if (c + 1 > r1) s[mt][nt][3] = -1e30f;
                }
            }
        }

#pragma unroll
        for (int mt = 0; mt < 2; mt++) {
            float t0 = -1e30f, t1 = -1e30f;
#pragma unroll
            for (int nt = 0; nt < 8; nt++) {
                t0 = fmaxf(t0, fmaxf(s[mt][nt][0], s[mt][nt][1]));
                t1 = fmaxf(t1, fmaxf(s[mt][nt][2], s[mt][nt][3]));
            }
            t0 = fmaxf(t0, __shfl_xor_sync(0xffffffffu, t0, 1));
            t0 = fmaxf(t0, __shfl_xor_sync(0xffffffffu, t0, 2));
            t1 = fmaxf(t1, __shfl_xor_sync(0xffffffffu, t1, 1));
            t1 = fmaxf(t1, __shfl_xor_sync(0xffffffffu, t1, 2));

            const float mn0 = fmaxf(m[mt][0], t0), mn1 = fmaxf(m[mt][1], t1);
            const float cr0 = fexp2(m[mt][0] - mn0), cr1 = fexp2(m[mt][1] - mn1);
            m[mt][0] = mn0; m[mt][1] = mn1;
            l[mt][0] *= cr0; l[mt][1] *= cr1;
#pragma unroll
            for (int nt = 0; nt < 8; nt++) {
                acc[mt][nt][0] *= cr0; acc[mt][nt][1] *= cr0;
                acc[mt][nt][2] *= cr1; acc[mt][nt][3] *= cr1;
            }
#pragma unroll
            for (int nt = 0; nt < 8; nt++) {
                float p0 = f2tf32(fexp2(s[mt][nt][0] - mn0));
                float p1 = f2tf32(fexp2(s[mt][nt][1] - mn0));
                float p2 = f2tf32(fexp2(s[mt][nt][2] - mn1));
                float p3 = f2tf32(fexp2(s[mt][nt][3] - mn1));
                l[mt][0] += p0 + p1; l[mt][1] += p2 + p3;
                s[mt][nt][0] = p0; s[mt][nt][1] = p1; s[mt][nt][2] = p2; s[mt][nt][3] = p3;
            }
        }

#pragma unroll
        for (int ks = 0; ks < 8; ks++) {
            uint32_t a0[4], a1[4];
#pragma unroll
            for (int mt = 0; mt < 2; mt++) {
                float v0 = __shfl_sync(0xffffffffu, s[mt][ks][0], src0);
                float v1 = __shfl_sync(0xffffffffu, s[mt][ks][1], src0);
                float v2 = __shfl_sync(0xffffffffu, s[mt][ks][2], src0);
                float v3 = __shfl_sync(0xffffffffu, s[mt][ks][3], src0);
                float w0 = __shfl_sync(0xffffffffu, s[mt][ks][0], src1);
                float w1 = __shfl_sync(0xffffffffu, s[mt][ks][1], src1);
                float w2 = __shfl_sync(0xffffffffu, s[mt][ks][2], src1);
                float w3 = __shfl_sync(0xffffffffu, s[mt][ks][3], src1);
                uint32_t* a = mt ? a1 : a0;
                a[0] = __float_as_uint(odd ? v1 : v0);
                a[1] = __float_as_uint(odd ? v3 : v2);
                a[2] = __float_as_uint(odd ? w1 : w0);
                a[3] = __float_as_uint(odd ? w3 : w2);
            }
#pragma unroll
            for (int nt = 0; nt < 8; nt++) {
                uint32_t b[2];
                b[0] = __float_as_uint(Vs[cur][8 * ks + tig][8 * nt + grp]);
                b[1] = __float_as_uint(Vs[cur][8 * ks + tig + 4][8 * nt + grp]);
                mma_tf32(acc[0][nt], a0, b);
                mma_tf32(acc[1][nt], a1, b);
            }
        }

        }  // causal skip
        __syncthreads();
    }

#pragma unroll
    for (int mt = 0; mt < 2; mt++) {
        float l0 = l[mt][0], l1 = l[mt][1];
        l0 += __shfl_xor_sync(0xffffffffu, l0, 1);
        l0 += __shfl_xor_sync(0xffffffffu, l0, 2);
        l1 += __shfl_xor_sync(0xffffffffu, l1, 1);
        l1 += __shfl_xor_sync(0xffffffffu, l1, 2);
        const float i0 = 1.f / l0, i1 = 1.f / l1;

        const int tq0 = qb * 128 + wm0 + 16 * mt + grp;
        float* o0 = g_O + (size_t)tq0 * DM + h * HD;
        float* o1 = o0 + (size_t)8 * DM;
#pragma unroll
        for (int nt = 0; nt < 8; nt++) {
            const int c  = 8 * nt + 2 * tig;
            const int p0 = (c & ~15) | perm16(c & 15);  // perm(c+1) = p0+4
            o0[p0]     = f2tf32(acc[mt][nt][0] * i0);
            o0[p0 + 4] = f2tf32(acc[mt][nt][1] * i0);
            o1[p0]     = f2tf32(acc[mt][nt][2] * i1);
            o1[p0 + 4] = f2tf32(acc[mt][nt][3] * i1);
        }
    }
}

// ---------------------------------------------------------------------------
extern "C" void kernel_launch(void* const* d_in, const int* in_sizes, int n_in,
                              void* d_out, int out_size)
{
    const float* x     = (const float*)d_in[0];
    const float* freqs = (const float*)d_in[1];
    const float* Wq    = (const float*)d_in[3];
    const float* Wk    = (const float*)d_in[4];
    const float* Wv    = (const float*)d_in[5];
    const float* Wo    = (const float*)d_in[6];
    float* out = (float*)d_out;

    conv_all<<<dim3(176, 64), 256>>>(x, Wq, Wk, Wv, Wo);

    gemm_tc<true><<<GEMM_CTAS, 256>>>(nullptr, freqs);     // persistent QKV (+RoPE)
    attn_tc_kernel<<<dim3(NH, TT / 128), dim3(128)>>>();
    gemm_tc<false><<<GEMM_CTAS, 256>>>(out, nullptr);      // persistent O-proj
}